// round 2
// baseline (speedup 1.0000x reference)
#include <cuda_runtime.h>

// Problem constants
#define NN  32
#define CC  64
#define TT  256
#define VV  50
#define HH  8
#define HCC 8
#define KA  65            // augmented K (64 channels + bias row)
#define TCH 8             // t-chunks for scores kernel
#define TPC (TT / TCH)    // 32 t per scores block
#define TB  2             // t per block in fused output kernel
#define TU  (TB * VV)     // 100

// Scratch (static device memory — no allocations allowed)
__device__ float g_wf[HH][CC][KA];                 // fused weights W_fh = Wo_h @ v_w, col 64 = Wo_h @ v_b
__device__ float g_spart[TCH][NN][HH][VV][VV];     // partial scores (20.5 MB)
__device__ float g_attn[NN][HH][VV][VV];           // tanh(scores)*alpha + global_attn

// Packed fp32x2 FMA (Blackwell FFMA2 — ptxas never auto-fuses this)
__device__ __forceinline__ float2 ffma2(float2 a, float2 b, float2 c) {
    float2 d;
    asm("{\n\t"
        ".reg .b64 ra, rb, rc;\n\t"
        "mov.b64 ra, {%2, %3};\n\t"
        "mov.b64 rb, {%4, %5};\n\t"
        "mov.b64 rc, {%6, %7};\n\t"
        "fma.rn.f32x2 rc, ra, rb, rc;\n\t"
        "mov.b64 {%0, %1}, rc;\n\t"
        "}"
        : "=f"(d.x), "=f"(d.y)
        : "f"(a.x), "f"(a.y), "f"(b.x), "f"(b.y), "f"(c.x), "f"(c.y));
    return d;
}

// ---------------------------------------------------------------------------
// Kernel 0: fuse o_w into v_w per head.  W_f[h][o][k<64] = sum_m o_w[o, h*64+m] * v_w[m, k]
//           W_f[h][o][64] = sum_m o_w[o, h*64+m] * v_b[m]
// ---------------------------------------------------------------------------
__global__ void k_fuse(const float* __restrict__ o_w, const float* __restrict__ v_w,
                       const float* __restrict__ v_b) {
    const int h = blockIdx.x;
    const int o = threadIdx.x;  // 64 threads
    __shared__ float svw[CC * CC];
    __shared__ float svb[CC];
    for (int i = o; i < CC * CC; i += blockDim.x) svw[i] = v_w[i];
    if (o < CC) svb[o] = v_b[o];
    __syncthreads();

    float wrow[CC];
#pragma unroll
    for (int m = 0; m < CC; m++) wrow[m] = o_w[o * (CC * HH) + h * CC + m];

    for (int k = 0; k < CC; k++) {
        float s = 0.f;
#pragma unroll
        for (int m = 0; m < CC; m++) s += wrow[m] * svw[m * CC + k];
        g_wf[h][o][k] = s;
    }
    float s = 0.f;
#pragma unroll
    for (int m = 0; m < CC; m++) s += wrow[m] * svb[m];
    g_wf[h][o][KA - 1] = s;
}

// ---------------------------------------------------------------------------
// Kernel 1: partial scores.  Block = (t-chunk, n).  For each t: project Q, K
// (64x50 each) in smem, accumulate S[h][u][v] += sum_cl Q[h*8+cl][u]*K[h*8+cl][v]
// in registers (float2 along v).
// dyn smem: sW 8192 | sB 128 | sX 6400 | sQK 6400  = 21120 floats = 84480 B
// ---------------------------------------------------------------------------
__global__ void __launch_bounds__(512) k_scores(
    const float* __restrict__ x_q, const float* __restrict__ x_kv,
    const float* __restrict__ q_w, const float* __restrict__ q_b,
    const float* __restrict__ k_w, const float* __restrict__ k_b) {
    extern __shared__ float sm[];
    float* sW  = sm;           // [2][64][64]
    float* sB  = sm + 8192;    // [2][64]
    float* sX  = sm + 8320;    // [2][64][50]
    float* sQK = sm + 14720;   // [2][64][50]

    const int tid = threadIdx.x;
    const int ch  = blockIdx.x;
    const int n   = blockIdx.y;
    const int t0  = ch * TPC;

    for (int i = tid; i < CC * CC; i += 512) {
        sW[i]        = q_w[i];
        sW[4096 + i] = k_w[i];
    }
    if (tid < CC) { sB[tid] = q_b[tid]; sB[64 + tid] = k_b[tid]; }

    float2 acc[20];
#pragma unroll
    for (int j = 0; j < 20; j++) acc[j] = make_float2(0.f, 0.f);

    __syncthreads();

    for (int tt = 0; tt < TPC; tt++) {
        const int t = t0 + tt;
        // load X_q, X_kv tiles (64x50 each)
        for (int i = tid; i < CC * VV; i += 512) {
            const int c = i / VV, v = i - c * VV;
            const long off = ((long)(n * CC + c) * TT + t) * VV + v;
            sX[i]        = x_q[off];
            sX[3200 + i] = x_kv[off];
        }
        __syncthreads();

        // Q = q_w @ Xq + q_b ; K = k_w @ Xkv + k_b   (float2 along u)
        for (int s = tid; s < 3200; s += 512) {
            const int p  = s / 1600;
            const int r  = s - p * 1600;
            const int c  = r / 25;
            const int up = r - c * 25;
            const float bias = sB[p * 64 + c];
            float2 a = make_float2(bias, bias);
            const float* w  = &sW[p * 4096 + c * 64];
            const float* xb = &sX[p * 3200 + 2 * up];
#pragma unroll
            for (int m = 0; m < 64; m++) {
                const float wv = w[m];
                const float2 xv = *(const float2*)(xb + m * VV);
                a = ffma2(make_float2(wv, wv), xv, a);
            }
            *(float2*)(&sQK[p * 3200 + c * VV + 2 * up]) = a;
        }
        __syncthreads();

        // S[h][u][v-pair] += sum_cl Q[h*8+cl][u] * K[h*8+cl][v-pair]
#pragma unroll
        for (int j = 0; j < 20; j++) {
            const int e = tid + j * 512;
            if (e < 10000) {
                const int h  = e / 1250;
                const int r  = e - h * 1250;
                const int u  = r / 25;
                const int vp = r - u * 25;
                const float* qb_ = &sQK[(h * 8) * VV + u];
                const float* kb_ = &sQK[3200 + (h * 8) * VV + 2 * vp];
                float2 a = acc[j];
#pragma unroll
                for (int cl = 0; cl < 8; cl++) {
                    const float  qv = qb_[cl * VV];
                    const float2 kv = *(const float2*)(kb_ + cl * VV);
                    a = ffma2(make_float2(qv, qv), kv, a);
                }
                acc[j] = a;
            }
        }
        __syncthreads();
    }

#pragma unroll
    for (int j = 0; j < 20; j++) {
        const int e = tid + j * 512;
        if (e < 10000) {
            const int h  = e / 1250;
            const int r  = e - h * 1250;
            const int u  = r / 25;
            const int vp = r - u * 25;
            *(float2*)&g_spart[ch][n][h][u][2 * vp] = acc[j];
        }
    }
}

// ---------------------------------------------------------------------------
// Kernel 1b: reduce partials, attn = tanh(S/(hc*T))*alpha[h] + global_attn[u,v]
// ---------------------------------------------------------------------------
__global__ void k_attn(const float* __restrict__ alphas, const float* __restrict__ gattn) {
    const int idx = blockIdx.x * blockDim.x + threadIdx.x;
    if (idx >= NN * HH * VV * VV) return;
    const int n  = idx / (HH * VV * VV);
    const int r  = idx - n * (HH * VV * VV);
    const int h  = r / (VV * VV);
    const int uv = r - h * (VV * VV);
    float s = 0.f;
#pragma unroll
    for (int c2 = 0; c2 < TCH; c2++)
        s += ((const float*)g_spart)[((long)(c2 * NN + n) * HH + h) * (VV * VV) + uv];
    const float a = tanhf(s * (1.0f / (HCC * TT))) * alphas[h] + gattn[uv];
    ((float*)g_attn)[idx] = a;
}

// ---------------------------------------------------------------------------
// Kernel 2: fused v-proj + values + o-proj.
// Block = (t-pair, n). out[:, t, :] = o_b + sum_h (W_fh @ X_aug) @ A_h
// dyn smem: sX 6500 | sU 6400 | sW 4160 | sA 2504 = 19564 floats = 78256 B
// ---------------------------------------------------------------------------
__global__ void __launch_bounds__(256) k_out(const float* __restrict__ x_kv,
                                             const float* __restrict__ o_b,
                                             float* __restrict__ out) {
    extern __shared__ float sm[];
    float* sX = sm;            // [65][100]  col = tl*50 + u, row 64 = 1.0
    float* sU = sm + 6500;     // [64][100]
    float* sW = sm + 12900;    // [64][65]
    float* sA = sm + 17060;    // [50][50] + 4 pad

    const int tid = threadIdx.x;
    const int n   = blockIdx.y;
    const int t0  = blockIdx.x * TB;

    // load X_aug
    for (int i = tid; i < CC * TU; i += 256) {
        const int c   = i / TU;
        const int col = i - c * TU;
        const int tl  = col / VV;
        const int u   = col - tl * VV;
        sX[i] = x_kv[((long)(n * CC + c) * TT + (t0 + tl)) * VV + u];
    }
    for (int i = tid; i < TU; i += 256) sX[CC * TU + i] = 1.0f;

    const int oq = tid >> 4;   // 0..15   (warp spans 2 oq values -> U broadcast)
    const int vq = tid & 15;   // 0..15   (active if < 13)
    float2 acc[16];            // [i(4 o)][tl(2)][j(2 v-pairs)]
#pragma unroll
    for (int i = 0; i < 16; i++) acc[i] = make_float2(0.f, 0.f);

    for (int h = 0; h < HH; h++) {
        __syncthreads();  // sU/sW/sA reuse fence (and covers X load at h=0)
        for (int i = tid; i < CC * KA; i += 256)
            sW[i] = ((const float*)g_wf)[h * CC * KA + i];
        for (int i = tid; i < VV * VV; i += 256)
            sA[i] = ((const float*)g_attn)[((long)n * HH + h) * (VV * VV) + i];
        if (tid < 4) sA[VV * VV + tid] = 0.f;  // pad
        __syncthreads();

        // stage A: U = W_fh @ X_aug  (two o-rows per slot, float2 along cols)
        for (int s = tid; s < 1600; s += 256) {
            const int o2 = s / 50;
            const int cg = s - o2 * 50;
            const float* w0 = &sW[(2 * o2) * KA];
            const float* w1 = w0 + KA;
            const float* xb = &sX[2 * cg];
            float2 a0 = make_float2(0.f, 0.f), a1 = make_float2(0.f, 0.f);
#pragma unroll
            for (int k = 0; k < KA; k++) {
                const float2 xv = *(const float2*)(xb + k * TU);
                a0 = ffma2(make_float2(w0[k], w0[k]), xv, a0);
                a1 = ffma2(make_float2(w1[k], w1[k]), xv, a1);
            }
            *(float2*)&sU[(2 * o2) * TU + 2 * cg]     = a0;
            *(float2*)&sU[(2 * o2 + 1) * TU + 2 * cg] = a1;
        }
        __syncthreads();

        // stage B: acc += U @ A_h   (4 o x 4 v x 2 t per thread)
        if (vq < 13) {
#pragma unroll
            for (int u = 0; u < VV; u++) {
                const float2 av0 = *(const float2*)&sA[u * VV + 4 * vq];
                const float2 av1 = *(const float2*)&sA[u * VV + 4 * vq + 2];
#pragma unroll
                for (int i = 0; i < 4; i++) {
                    const int o = oq * 4 + i;
                    const float u0 = sU[o * TU + u];
                    const float u1 = sU[o * TU + VV + u];
                    acc[i * 4 + 0] = ffma2(make_float2(u0, u0), av0, acc[i * 4 + 0]);
                    acc[i * 4 + 1] = ffma2(make_float2(u0, u0), av1, acc[i * 4 + 1]);
                    acc[i * 4 + 2] = ffma2(make_float2(u1, u1), av0, acc[i * 4 + 2]);
                    acc[i * 4 + 3] = ffma2(make_float2(u1, u1), av1, acc[i * 4 + 3]);
                }
            }
        }
    }

    // epilogue: out[n][o][t0+tl][v] = acc + o_b[o]
    if (vq < 13) {
#pragma unroll
        for (int i = 0; i < 4; i++) {
            const int o = oq * 4 + i;
            const float ob = o_b[o];
#pragma unroll
            for (int tl = 0; tl < TB; tl++) {
#pragma unroll
                for (int j = 0; j < 2; j++) {
                    const int v = 4 * vq + 2 * j;
                    if (v < VV) {
                        const float2 r = acc[i * 4 + 2 * tl + j];
                        const long off = ((long)(n * CC + o) * TT + t0 + tl) * VV + v;
                        out[off]     = r.x + ob;
                        out[off + 1] = r.y + ob;
                    }
                }
            }
        }
    }
}

// ---------------------------------------------------------------------------
extern "C" void kernel_launch(void* const* d_in, const int* in_sizes, int n_in,
                              void* d_out, int out_size) {
    const float* x_q    = (const float*)d_in[0];
    const float* x_kv   = (const float*)d_in[1];
    const float* q_w    = (const float*)d_in[2];
    const float* q_b    = (const float*)d_in[3];
    const float* k_w    = (const float*)d_in[4];
    const float* k_b    = (const float*)d_in[5];
    const float* v_w    = (const float*)d_in[6];
    const float* v_b    = (const float*)d_in[7];
    const float* o_w    = (const float*)d_in[8];
    const float* o_b    = (const float*)d_in[9];
    const float* alphas = (const float*)d_in[10];
    const float* gattn  = (const float*)d_in[11];
    float* out = (float*)d_out;

    const int smem1 = 21120 * sizeof(float);  // 84480 B
    const int smem2 = 19564 * sizeof(float);  // 78256 B
    cudaFuncSetAttribute(k_scores, cudaFuncAttributeMaxDynamicSharedMemorySize, smem1);
    cudaFuncSetAttribute(k_out,    cudaFuncAttributeMaxDynamicSharedMemorySize, smem2);

    k_fuse<<<HH, 64>>>(o_w, v_w, v_b);
    k_scores<<<dim3(TCH, NN), 512, smem1>>>(x_q, x_kv, q_w, q_b, k_w, k_b);
    k_attn<<<(NN * HH * VV * VV + 255) / 256, 256>>>(alphas, gattn);
    k_out<<<dim3(TT / TB, NN), 256, smem2>>>(x_kv, o_b, out);
}

// round 4
// speedup vs baseline: 1.6888x; 1.6888x over previous
#include <cuda_runtime.h>

// Problem constants
#define NN  32
#define CC  64
#define TT  256
#define VV  50
#define HH  8
#define HCC 8
#define KA  65            // augmented K (64 channels + bias row)
#define TCH 8             // t-chunks for scores kernel
#define TPC (TT / TCH)    // 32 t per scores block
#define TB  2             // t per block in fused output kernel

// Scratch (static device memory — no allocations allowed)
__device__ float g_wf[HH][CC][KA];                 // fused weights W_fh = Wo_h @ v_w (+ bias col)
__device__ float g_spart[TCH][NN][HH][VV][VV];     // partial scores
__device__ float g_attn[NN][HH][VV][VV];           // tanh(scores)*alpha + global_attn

// Packed fp32x2 FMA with scalar multiplier broadcast (Blackwell FFMA2)
__device__ __forceinline__ float2 ffma2s(float a, float2 b, float2 c) {
    float2 d;
    asm("{\n\t"
        ".reg .b64 ra, rb, rc;\n\t"
        "mov.b64 ra, {%2, %2};\n\t"
        "mov.b64 rb, {%3, %4};\n\t"
        "mov.b64 rc, {%5, %6};\n\t"
        "fma.rn.f32x2 rc, ra, rb, rc;\n\t"
        "mov.b64 {%0, %1}, rc;\n\t"
        "}"
        : "=f"(d.x), "=f"(d.y)
        : "f"(a), "f"(b.x), "f"(b.y), "f"(c.x), "f"(c.y));
    return d;
}

__device__ __forceinline__ float4 ffma4s(float a, float4 b, float4 c) {
    float2 lo = ffma2s(a, make_float2(b.x, b.y), make_float2(c.x, c.y));
    float2 hi = ffma2s(a, make_float2(b.z, b.w), make_float2(c.z, c.w));
    return make_float4(lo.x, lo.y, hi.x, hi.y);
}

// ---------------------------------------------------------------------------
// Kernel 0: fuse o_w into v_w per head.
// ---------------------------------------------------------------------------
__global__ void k_fuse(const float* __restrict__ o_w, const float* __restrict__ v_w,
                       const float* __restrict__ v_b) {
    const int h = blockIdx.x;
    const int o = threadIdx.x;  // 64 threads
    __shared__ float svw[CC * CC];
    __shared__ float svb[CC];
    for (int i = o; i < CC * CC; i += blockDim.x) svw[i] = v_w[i];
    if (o < CC) svb[o] = v_b[o];
    __syncthreads();

    float wrow[CC];
#pragma unroll
    for (int m = 0; m < CC; m++) wrow[m] = o_w[o * (CC * HH) + h * CC + m];

    for (int k = 0; k < CC; k++) {
        float s = 0.f;
#pragma unroll
        for (int m = 0; m < CC; m++) s += wrow[m] * svw[m * CC + k];
        g_wf[h][o][k] = s;
    }
    float s = 0.f;
#pragma unroll
    for (int m = 0; m < CC; m++) s += wrow[m] * svb[m];
    g_wf[h][o][KA - 1] = s;
}

// ---------------------------------------------------------------------------
// Kernel 1: partial scores with register tiling.
// smem: sW [2][64][65]=8320 | sB 128 | sX [2][64][50]=6400 | sQ [2][64][52]=6656
// total 21504 floats = 86016 B
// ---------------------------------------------------------------------------
__global__ void __launch_bounds__(512, 1) k_scores(
    const float* __restrict__ x_q, const float* __restrict__ x_kv,
    const float* __restrict__ q_w, const float* __restrict__ q_b,
    const float* __restrict__ k_w, const float* __restrict__ k_b) {
    extern __shared__ float sm[];
    float* sW = sm;           // [p][64][65] padded rows (bank-conflict-free broadcasts)
    float* sB = sm + 8320;
    float* sX = sm + 8448;    // [p][64][50]
    float* sQ = sm + 14848;   // [p][64][52] padded (16B-aligned rows, zero pad cols)

    const int tid = threadIdx.x;
    const int ch  = blockIdx.x;
    const int n   = blockIdx.y;
    const int t0  = ch * TPC;

    for (int i = tid; i < CC * CC; i += 512) {
        const int c = i >> 6, m = i & 63;
        sW[c * 65 + m]        = q_w[i];
        sW[4160 + c * 65 + m] = k_w[i];
    }
    if (tid < CC) { sB[tid] = q_b[tid]; sB[64 + tid] = k_b[tid]; }
    // zero pad cols 50,51 of sQ (written once; projection never touches them)
    for (int i = tid; i < 2 * 64 * 2; i += 512) {
        const int p = i >> 7, r = (i >> 1) & 63, c = i & 1;
        sQ[p * 3328 + r * 52 + 50 + c] = 0.f;
    }

    // scores slot decomposition: 8h x 13(u-quad) x 13(v-quad) = 1352 slots
    int sh[3], su[3], sv[3];
    bool val[3];
    float4 acc[3][4];
#pragma unroll
    for (int it = 0; it < 3; it++) {
        const int s = tid + it * 512;
        val[it] = (s < 1352);
        const int ss = val[it] ? s : 0;
        sh[it] = ss / 169;
        const int r = ss % 169;
        su[it] = (r / 13) * 4;
        sv[it] = (r % 13) * 4;
#pragma unroll
        for (int i = 0; i < 4; i++) acc[it][i] = make_float4(0.f, 0.f, 0.f, 0.f);
    }

    // projection mapping: 400 active threads, 8 c-rows x 2 u-cols each
    const bool pact = tid < 400;
    const int  pp   = tid / 200;
    const int  prem = tid % 200;
    const int  pog  = (prem / 25) * 8;
    const int  pcp  = (prem % 25) * 2;

    __syncthreads();

    for (int tt = 0; tt < TPC; tt++) {
        const int t = t0 + tt;
        for (int i = tid; i < 6400; i += 512) {
            const int half = i / 3200;
            const int r = i - half * 3200;
            const int c = r / 50, v = r - c * 50;
            const float* src = half ? x_kv : x_q;
            sX[i] = src[((long)(n * CC + c) * TT + t) * VV + v];
        }
        __syncthreads();

        if (pact) {
            float2 a[8];
            const float* wb = sW + pp * 4160 + pog * 65;
            const float* bb = sB + pp * 64 + pog;
#pragma unroll
            for (int j = 0; j < 8; j++) { const float b = bb[j]; a[j] = make_float2(b, b); }
            const float* xb = sX + pp * 3200 + pcp;
#pragma unroll
            for (int m = 0; m < 64; m++) {
                const float2 xv = *(const float2*)(xb + m * 50);
#pragma unroll
                for (int j = 0; j < 8; j++) a[j] = ffma2s(wb[j * 65 + m], xv, a[j]);
            }
            float* qb = sQ + pp * 3328 + pog * 52 + pcp;
#pragma unroll
            for (int j = 0; j < 8; j++) *(float2*)(qb + j * 52) = a[j];
        }
        __syncthreads();

#pragma unroll
        for (int it = 0; it < 3; it++) {
            if (val[it]) {
                const float* qb = sQ + (sh[it] * 8) * 52 + su[it];
                const float* kb = sQ + 3328 + (sh[it] * 8) * 52 + sv[it];
#pragma unroll
                for (int cl = 0; cl < 8; cl++) {
                    const float4 kv = *(const float4*)(kb + cl * 52);
#pragma unroll
                    for (int i = 0; i < 4; i++)
                        acc[it][i] = ffma4s(qb[cl * 52 + i], kv, acc[it][i]);
                }
            }
        }
        __syncthreads();
    }

#pragma unroll
    for (int it = 0; it < 3; it++) {
        if (val[it]) {
#pragma unroll
            for (int i = 0; i < 4; i++) {
                const int u = su[it] + i;
                if (u < VV) {
                    float* dst = &g_spart[ch][n][sh[it]][u][sv[it]];
                    const float4 a4 = acc[it][i];
                    dst[0] = a4.x; dst[1] = a4.y;
                    if (sv[it] + 2 < VV) { dst[2] = a4.z; dst[3] = a4.w; }
                }
            }
        }
    }
}

// ---------------------------------------------------------------------------
// Kernel 1b: reduce partials, attn = tanh(S/(hc*T))*alpha[h] + global_attn
// ---------------------------------------------------------------------------
__global__ void k_attn(const float* __restrict__ alphas, const float* __restrict__ gattn) {
    const int idx = blockIdx.x * blockDim.x + threadIdx.x;
    if (idx >= NN * HH * VV * VV) return;
    const int n  = idx / (HH * VV * VV);
    const int r  = idx - n * (HH * VV * VV);
    const int h  = r / (VV * VV);
    const int uv = r - h * (VV * VV);
    float s = 0.f;
#pragma unroll
    for (int c2 = 0; c2 < TCH; c2++)
        s += ((const float*)g_spart)[((long)(c2 * NN + n) * HH + h) * (VV * VV) + uv];
    const float a = tanhf(s * (1.0f / (HCC * TT))) * alphas[h] + gattn[uv];
    ((float*)g_attn)[idx] = a;
}

// ---------------------------------------------------------------------------
// Kernel 2: fused v-proj + values + o-proj, register-tiled.
// smem: sX [65][104]=6760 | sU [64][104]=6656 | sW [64][65]=4160 | sA [52][52]=2704
// total 20280 floats = 81120 B  (2 blocks/SM)
// padded layout: col index pc -> (tl = pc/52, u = pc%52); u>=50 cols are zero.
// ---------------------------------------------------------------------------
__global__ void __launch_bounds__(256, 2) k_out(const float* __restrict__ x_kv,
                                                const float* __restrict__ o_b,
                                                float* __restrict__ out) {
    extern __shared__ float sm[];
    float* sX = sm;            // [65][104]
    float* sU = sm + 6760;     // [64][104]
    float* sW = sm + 13416;    // [64][65]
    float* sA = sm + 17576;    // [52][52] (rows/cols >=50 zeroed)

    const int tid = threadIdx.x;
    const int n   = blockIdx.y;
    const int t0  = blockIdx.x * TB;

    // load X_aug into padded layout (zeros in pad cols, ones row = 64)
    for (int i = tid; i < 65 * 104; i += 256) {
        const int row = i / 104, pc = i - row * 104;
        const int tl = pc / 52, u = pc - tl * 52;
        float v = 0.f;
        if (u < VV)
            v = (row == 64) ? 1.f
                            : x_kv[((long)(n * CC + row) * TT + t0 + tl) * VV + u];
        sX[i] = v;
    }

    // shared thread mapping for stages A and B (208 active threads)
    const bool act = tid < 208;
    const int  og  = (tid / 26) * 8;      // 8 o-rows per thread
    const int  r26 = tid % 26;
    const int  acq = r26 * 4;             // stage A: 4 padded cols
    const int  btl = r26 / 13;            // stage B: t within pair
    const int  bvq = (r26 % 13) * 4;      // stage B: 4 v's

    float4 accB[8];
#pragma unroll
    for (int j = 0; j < 8; j++) accB[j] = make_float4(0.f, 0.f, 0.f, 0.f);

    for (int h = 0; h < HH; h++) {
        __syncthreads();  // prev stage B done with sU/sA/sW (covers X load at h=0)
        for (int i = tid; i < CC * KA; i += 256)
            sW[i] = ((const float*)g_wf)[h * (CC * KA) + i];
        for (int i = tid; i < 52 * 52; i += 256) {
            const int row = i / 52, col = i - row * 52;
            sA[i] = (row < VV && col < VV) ? g_attn[n][h][row][col] : 0.f;
        }
        __syncthreads();

        // stage A: U = W_fh @ X_aug.  8 o-rows x 4 cols per thread.
        if (act) {
            float4 a[8];
#pragma unroll
            for (int j = 0; j < 8; j++) a[j] = make_float4(0.f, 0.f, 0.f, 0.f);
            const float* wb = sW + og * 65;
            const float* xb = sX + acq;
#pragma unroll
            for (int k = 0; k < KA; k++) {
                const float4 xv = *(const float4*)(xb + k * 104);
#pragma unroll
                for (int j = 0; j < 8; j++) a[j] = ffma4s(wb[j * 65 + k], xv, a[j]);
            }
            float* ub = sU + og * 104 + acq;
#pragma unroll
            for (int j = 0; j < 8; j++) *(float4*)(ub + j * 104) = a[j];
        }
        __syncthreads();

        // stage B: acc += U_h @ A_h.  8 o-rows x 4 v x 1 tl per thread, u blocked by 4.
        if (act) {
            const float* ub = sU + og * 104 + btl * 52;
            const float* ab = sA + bvq;
            for (int uu = 0; uu < 52; uu += 4) {
                float4 u4[8];
#pragma unroll
                for (int j = 0; j < 8; j++) u4[j] = *(const float4*)(ub + j * 104 + uu);
#pragma unroll
                for (int i = 0; i < 4; i++) {
                    const float4 av = *(const float4*)(ab + (uu + i) * 52);
#pragma unroll
                    for (int j = 0; j < 8; j++) {
                        const float us = (i == 0) ? u4[j].x : (i == 1) ? u4[j].y
                                        : (i == 2) ? u4[j].z : u4[j].w;
                        accB[j] = ffma4s(us, av, accB[j]);
                    }
                }
            }
        }
    }

    // epilogue
    if (act) {
#pragma unroll
        for (int j = 0; j < 8; j++) {
            const int o = og + j;
            const float ob = o_b[o];
            const long base = ((long)(n * CC + o) * TT + t0 + btl) * VV + bvq;
            out[base]     = accB[j].x + ob;
            out[base + 1] = accB[j].y + ob;
            if (bvq + 2 < VV) {
                out[base + 2] = accB[j].z + ob;
                out[base + 3] = accB[j].w + ob;
            }
        }
    }
}

// ---------------------------------------------------------------------------
extern "C" void kernel_launch(void* const* d_in, const int* in_sizes, int n_in,
                              void* d_out, int out_size) {
    const float* x_q    = (const float*)d_in[0];
    const float* x_kv   = (const float*)d_in[1];
    const float* q_w    = (const float*)d_in[2];
    const float* q_b    = (const float*)d_in[3];
    const float* k_w    = (const float*)d_in[4];
    const float* k_b    = (const float*)d_in[5];
    const float* v_w    = (const float*)d_in[6];
    const float* v_b    = (const float*)d_in[7];
    const float* o_w    = (const float*)d_in[8];
    const float* o_b    = (const float*)d_in[9];
    const float* alphas = (const float*)d_in[10];
    const float* gattn  = (const float*)d_in[11];
    float* out = (float*)d_out;

    const int smem1 = 21504 * sizeof(float);  // 86016 B
    const int smem2 = 20280 * sizeof(float);  // 81120 B
    cudaFuncSetAttribute(k_scores, cudaFuncAttributeMaxDynamicSharedMemorySize, smem1);
    cudaFuncSetAttribute(k_out,    cudaFuncAttributeMaxDynamicSharedMemorySize, smem2);

    k_fuse<<<HH, 64>>>(o_w, v_w, v_b);
    k_scores<<<dim3(TCH, NN), 512, smem1>>>(x_q, x_kv, q_w, q_b, k_w, k_b);
    k_attn<<<(NN * HH * VV * VV + 255) / 256, 256>>>(alphas, gattn);
    k_out<<<dim3(TT / TB, NN), 256, smem2>>>(x_kv, o_b, out);
}